// round 3
// baseline (speedup 1.0000x reference)
#include <cuda_runtime.h>
#include <math.h>

#define B 192
#define D 2048
#define H 128
#define LOG2PI 1.8378770664093453f
#define IG 8   // i-rows per main-kernel block

// Scratch (device globals — no allocation allowed)
__device__ __align__(16) float g_h1[B * 2 * H];
__device__ __align__(16) float g_h2[B * 2 * H];
__device__ __align__(16) float g_mu[B * D];
__device__ __align__(16) float g_scale[B * D];
__device__ float g_lvpart[B * 8];

// ---------------------------------------------------------------------------
// Kernel 1: h1 = relu(q @ w1^T + b1), both heads (cols 0..127 mu, 128..255 lv).
// 4x4 register-tiled warps: warp computes 4 rows x 4 cols, lanes split K=2048.
// ---------------------------------------------------------------------------
__global__ void __launch_bounds__(256) gemm1_kernel(
    const float* __restrict__ q,
    const float* __restrict__ mw, const float* __restrict__ mb,
    const float* __restrict__ lw, const float* __restrict__ lb)
{
    int warp = threadIdx.x >> 5;
    int lane = threadIdx.x & 31;
    int cg   = blockIdx.x * 8 + warp;   // colgroup 0..63
    int row0 = blockIdx.y * 4;
    int col0 = cg * 4;

    const float* wbase;
    const float* bbase;
    int clocal;
    if (col0 < H) { wbase = mw; bbase = mb; clocal = col0;     }
    else          { wbase = lw; bbase = lb; clocal = col0 - H; }

    const float4* q4 = (const float4*)q;
    const float4* w4 = (const float4*)wbase;

    float acc[4][4];
    #pragma unroll
    for (int r = 0; r < 4; ++r)
        #pragma unroll
        for (int c = 0; c < 4; ++c) acc[r][c] = 0.f;

    #pragma unroll
    for (int it = 0; it < (D / 4) / 32; ++it) {   // 16 iters
        int k4 = lane + it * 32;
        float4 a[4], b[4];
        #pragma unroll
        for (int r = 0; r < 4; ++r) a[r] = q4[(size_t)(row0 + r) * (D / 4) + k4];
        #pragma unroll
        for (int c = 0; c < 4; ++c) b[c] = w4[(size_t)(clocal + c) * (D / 4) + k4];
        #pragma unroll
        for (int r = 0; r < 4; ++r)
            #pragma unroll
            for (int c = 0; c < 4; ++c)
                acc[r][c] += a[r].x * b[c].x + a[r].y * b[c].y
                           + a[r].z * b[c].z + a[r].w * b[c].w;
    }

    float bv[4];
    #pragma unroll
    for (int c = 0; c < 4; ++c) bv[c] = bbase[clocal + c];

    #pragma unroll
    for (int r = 0; r < 4; ++r)
        #pragma unroll
        for (int c = 0; c < 4; ++c) {
            float v = acc[r][c];
            #pragma unroll
            for (int o = 16; o; o >>= 1) v += __shfl_xor_sync(0xffffffffu, v, o);
            if (lane == 0)
                g_h1[(row0 + r) * 256 + col0 + c] = fmaxf(v + bv[c], 0.f);
        }
}

// ---------------------------------------------------------------------------
// Kernel 2: h2 = relu(h1 @ w2^T + b2), block per row
// ---------------------------------------------------------------------------
__global__ void __launch_bounds__(256) gemm2_kernel(
    const float* __restrict__ mw, const float* __restrict__ mb,
    const float* __restrict__ lw, const float* __restrict__ lb)
{
    __shared__ float s[256];
    int row = blockIdx.x;
    int tid = threadIdx.x;
    s[tid] = g_h1[row * 256 + tid];
    __syncthreads();

    float acc;
    const float* w;
    const float* h;
    if (tid < H) { acc = mb[tid];     w = mw + (size_t)tid * H;       h = s;     }
    else         { acc = lb[tid - H]; w = lw + (size_t)(tid - H) * H; h = s + H; }
    #pragma unroll 16
    for (int k = 0; k < H; ++k) acc += h[k] * w[k];
    g_h2[row * 256 + tid] = fmaxf(acc, 0.f);
}

// ---------------------------------------------------------------------------
// Kernel 3: layer-3 for both heads, 4 rows per block, h2 half-row in smem.
//   mu head  (bx 0..7):  g_mu = relu(...)
//   lv head  (bx 8..15): g_scale = exp(0.25*lv), deterministic partial sum(lv)
// ---------------------------------------------------------------------------
__global__ void __launch_bounds__(256) gemm3_kernel(
    const float* __restrict__ mw, const float* __restrict__ mb,
    const float* __restrict__ lw, const float* __restrict__ lb)
{
    __shared__ float4 s4[4][32];       // 4 rows x 128 floats (one head half)
    __shared__ float red[8][4];

    int tid  = threadIdx.x;
    int row0 = blockIdx.y * 4;
    int head = blockIdx.x >> 3;        // 0 = mu, 1 = lv

    if (tid < 128) {
        int r  = tid >> 5;
        int kk = tid & 31;
        s4[r][kk] = ((const float4*)(g_h2 + (row0 + r) * 256 + head * H))[kk];
    }
    __syncthreads();

    int d = (blockIdx.x & 7) * 256 + tid;         // 0..2047 within head
    const float* wrow = (head ? lw : mw) + (size_t)d * H;
    const float* bptr = head ? lb : mb;

    float acc0 = 0.f, acc1 = 0.f, acc2 = 0.f, acc3 = 0.f;
    #pragma unroll
    for (int kk = 0; kk < 32; ++kk) {
        float4 w = ((const float4*)wrow)[kk];
        float4 h0 = s4[0][kk], h1 = s4[1][kk], h2v = s4[2][kk], h3 = s4[3][kk];
        acc0 += w.x * h0.x + w.y * h0.y + w.z * h0.z + w.w * h0.w;
        acc1 += w.x * h1.x + w.y * h1.y + w.z * h1.z + w.w * h1.w;
        acc2 += w.x * h2v.x + w.y * h2v.y + w.z * h2v.z + w.w * h2v.w;
        acc3 += w.x * h3.x + w.y * h3.y + w.z * h3.z + w.w * h3.w;
    }
    float bias = bptr[d];
    float v[4] = { fmaxf(acc0 + bias, 0.f), fmaxf(acc1 + bias, 0.f),
                   fmaxf(acc2 + bias, 0.f), fmaxf(acc3 + bias, 0.f) };

    if (!head) {
        #pragma unroll
        for (int r = 0; r < 4; ++r)
            g_mu[(size_t)(row0 + r) * D + d] = v[r];
    } else {
        #pragma unroll
        for (int r = 0; r < 4; ++r)
            g_scale[(size_t)(row0 + r) * D + d] = expf(0.25f * v[r]);

        int lane = tid & 31, wid = tid >> 5;
        #pragma unroll
        for (int r = 0; r < 4; ++r) {
            float s = v[r];
            #pragma unroll
            for (int o = 16; o; o >>= 1) s += __shfl_xor_sync(0xffffffffu, s, o);
            if (lane == 0) red[wid][r] = s;
        }
        __syncthreads();
        if (tid == 0) {
            #pragma unroll
            for (int r = 0; r < 4; ++r) {
                float s = 0.f;
                #pragma unroll
                for (int k = 0; k < 8; ++k) s += red[k][r];
                g_lvpart[(row0 + r) * 8 + (blockIdx.x & 7)] = s;
            }
        }
    }
}

// ---------------------------------------------------------------------------
// Kernel 4 (HBM-bound mainloop): one block per (j, group of IG=8 i-rows).
// mu/scale for column j loaded into smem ONCE, reused for 8 eps rows:
// cuts mu/scale L2 traffic 8x (604 MB -> 75 MB) so LTS stops co-binding.
//   p[i,j,:] = mu[j,:] + eps[i,j,:] * scale[j,:]
//   log_prob[i,j] = -0.5 * sum(eps^2) - 0.25*sum(lv[j]) - 0.5*D*log2pi
// grid = B*(B/IG) = 4608 blocks x 256 threads.
// ---------------------------------------------------------------------------
__global__ void __launch_bounds__(256) main_kernel(
    const float* __restrict__ eps,
    float* __restrict__ p,
    float* __restrict__ lp)
{
    __shared__ float4 sm[D / 4];     // 8 KB mu
    __shared__ float4 ss[D / 4];     // 8 KB scale
    __shared__ float red[8][IG];
    __shared__ float s_t;

    int j  = blockIdx.x % B;
    int ig = blockIdx.x / B;         // 0..23
    int tid = threadIdx.x;

    {
        const float4* m4 = (const float4*)g_mu    + (size_t)j * (D / 4);
        const float4* s4 = (const float4*)g_scale + (size_t)j * (D / 4);
        #pragma unroll
        for (int it = 0; it < 2; ++it) {
            sm[tid + it * 256] = m4[tid + it * 256];
            ss[tid + it * 256] = s4[tid + it * 256];
        }
    }
    if (tid == 0) {
        float sum = 0.f;
        #pragma unroll
        for (int k = 0; k < 8; ++k) sum += g_lvpart[j * 8 + k];
        s_t = -0.25f * sum - 0.5f * (float)D * LOG2PI;
    }
    __syncthreads();

    float acc[IG];
    #pragma unroll
    for (int r = 0; r < IG; ++r) {
        size_t row = (size_t)(ig * IG + r) * B + j;
        const float4* e4 = (const float4*)eps + row * (D / 4);
        float4*       p4 = (float4*)p        + row * (D / 4);
        float a = 0.f;
        #pragma unroll
        for (int it = 0; it < 2; ++it) {
            int idx = tid + it * 256;
            float4 e = __ldcs(&e4[idx]);
            float4 m = sm[idx];
            float4 s = ss[idx];
            float4 o;
            o.x = fmaf(e.x, s.x, m.x);
            o.y = fmaf(e.y, s.y, m.y);
            o.z = fmaf(e.z, s.z, m.z);
            o.w = fmaf(e.w, s.w, m.w);
            __stcs(&p4[idx], o);
            a += e.x * e.x + e.y * e.y + e.z * e.z + e.w * e.w;
        }
        acc[r] = a;
    }

    int lane = tid & 31, wid = tid >> 5;
    #pragma unroll
    for (int r = 0; r < IG; ++r) {
        float v = acc[r];
        #pragma unroll
        for (int o = 16; o; o >>= 1) v += __shfl_xor_sync(0xffffffffu, v, o);
        if (lane == 0) red[wid][r] = v;
    }
    __syncthreads();
    if (tid < IG) {
        float v = 0.f;
        #pragma unroll
        for (int k = 0; k < 8; ++k) v += red[k][tid];
        lp[(size_t)(ig * IG + tid) * B + j] = -0.5f * v + s_t;
    }
}

// ---------------------------------------------------------------------------
extern "C" void kernel_launch(void* const* d_in, const int* in_sizes, int n_in,
                              void* d_out, int out_size)
{
    const float* q     = (const float*)d_in[0];
    const float* eps   = (const float*)d_in[1];
    const float* mu_w1 = (const float*)d_in[2];
    const float* mu_b1 = (const float*)d_in[3];
    const float* mu_w2 = (const float*)d_in[4];
    const float* mu_b2 = (const float*)d_in[5];
    const float* mu_w3 = (const float*)d_in[6];
    const float* mu_b3 = (const float*)d_in[7];
    const float* lv_w1 = (const float*)d_in[8];
    const float* lv_b1 = (const float*)d_in[9];
    const float* lv_w2 = (const float*)d_in[10];
    const float* lv_b2 = (const float*)d_in[11];
    const float* lv_w3 = (const float*)d_in[12];
    const float* lv_b3 = (const float*)d_in[13];

    float* p  = (float*)d_out;                       // [B, B, D]
    float* lp = (float*)d_out + (size_t)B * B * D;   // [B, B]

    gemm1_kernel<<<dim3(8, 48), 256>>>(q, mu_w1, mu_b1, lv_w1, lv_b1);
    gemm2_kernel<<<B, 256>>>(mu_w2, mu_b2, lv_w2, lv_b2);
    gemm3_kernel<<<dim3(16, 48), 256>>>(mu_w3, mu_b3, lv_w3, lv_b3);
    main_kernel<<<B * (B / IG), 256>>>(eps, p, lp);
}

// round 4
// speedup vs baseline: 1.3773x; 1.3773x over previous
#include <cuda_runtime.h>
#include <math.h>

#define B 192
#define D 2048
#define H 128
#define LOG2PI 1.8378770664093453f
#define IG 4   // i-rows per main-kernel block

// Scratch (device globals — no allocation allowed)
__device__ __align__(16) float g_h1[B * 2 * H];
__device__ __align__(16) float g_h2[B * 2 * H];
__device__ __align__(16) float g_mu[B * D];
__device__ __align__(16) float g_scale[B * D];
__device__ float g_lvpart[B * 8];

// ---------------------------------------------------------------------------
// Kernel 1: h1 = relu(q @ w1^T + b1), both heads (cols 0..127 mu, 128..255 lv).
// 4x4 register-tiled warps: warp computes 4 rows x 4 cols, lanes split K=2048.
// ---------------------------------------------------------------------------
__global__ void __launch_bounds__(256) gemm1_kernel(
    const float* __restrict__ q,
    const float* __restrict__ mw, const float* __restrict__ mb,
    const float* __restrict__ lw, const float* __restrict__ lb)
{
    int warp = threadIdx.x >> 5;
    int lane = threadIdx.x & 31;
    int cg   = blockIdx.x * 8 + warp;   // colgroup 0..63
    int row0 = blockIdx.y * 4;
    int col0 = cg * 4;

    const float* wbase;
    const float* bbase;
    int clocal;
    if (col0 < H) { wbase = mw; bbase = mb; clocal = col0;     }
    else          { wbase = lw; bbase = lb; clocal = col0 - H; }

    const float4* q4 = (const float4*)q;
    const float4* w4 = (const float4*)wbase;

    float acc[4][4];
    #pragma unroll
    for (int r = 0; r < 4; ++r)
        #pragma unroll
        for (int c = 0; c < 4; ++c) acc[r][c] = 0.f;

    #pragma unroll
    for (int it = 0; it < (D / 4) / 32; ++it) {   // 16 iters
        int k4 = lane + it * 32;
        float4 a[4], b[4];
        #pragma unroll
        for (int r = 0; r < 4; ++r) a[r] = q4[(size_t)(row0 + r) * (D / 4) + k4];
        #pragma unroll
        for (int c = 0; c < 4; ++c) b[c] = w4[(size_t)(clocal + c) * (D / 4) + k4];
        #pragma unroll
        for (int r = 0; r < 4; ++r)
            #pragma unroll
            for (int c = 0; c < 4; ++c)
                acc[r][c] += a[r].x * b[c].x + a[r].y * b[c].y
                           + a[r].z * b[c].z + a[r].w * b[c].w;
    }

    float bv[4];
    #pragma unroll
    for (int c = 0; c < 4; ++c) bv[c] = bbase[clocal + c];

    #pragma unroll
    for (int r = 0; r < 4; ++r)
        #pragma unroll
        for (int c = 0; c < 4; ++c) {
            float v = acc[r][c];
            #pragma unroll
            for (int o = 16; o; o >>= 1) v += __shfl_xor_sync(0xffffffffu, v, o);
            if (lane == 0)
                g_h1[(row0 + r) * 256 + col0 + c] = fmaxf(v + bv[c], 0.f);
        }
}

// ---------------------------------------------------------------------------
// Kernel 2: h2 = relu(h1 @ w2^T + b2). 8 rows per block (24 blocks): each
// w2 element loaded once per thread and reused across 8 rows.
// thread tid owns output column tid for all 8 rows.
// ---------------------------------------------------------------------------
__global__ void __launch_bounds__(256) gemm2_kernel(
    const float* __restrict__ mw, const float* __restrict__ mb,
    const float* __restrict__ lw, const float* __restrict__ lb)
{
    __shared__ float s[8][256];
    int row0 = blockIdx.x * 8;
    int tid = threadIdx.x;

    #pragma unroll
    for (int r = 0; r < 8; ++r)
        s[r][tid] = g_h1[(row0 + r) * 256 + tid];
    __syncthreads();

    const float* w;
    float bias;
    int hoff;
    if (tid < H) { w = mw + (size_t)tid * H;       bias = mb[tid];     hoff = 0; }
    else         { w = lw + (size_t)(tid - H) * H; bias = lb[tid - H]; hoff = H; }

    float acc[8];
    #pragma unroll
    for (int r = 0; r < 8; ++r) acc[r] = bias;

    #pragma unroll 8
    for (int k = 0; k < H; ++k) {
        float wv = w[k];
        #pragma unroll
        for (int r = 0; r < 8; ++r) acc[r] += s[r][hoff + k] * wv;
    }
    #pragma unroll
    for (int r = 0; r < 8; ++r)
        g_h2[(row0 + r) * 256 + tid] = fmaxf(acc[r], 0.f);
}

// ---------------------------------------------------------------------------
// Kernel 3: layer-3 for both heads, 8 rows per block, h2 half-rows in smem.
//   mu head  (bx 0..7):  g_mu = relu(...)
//   lv head  (bx 8..15): g_scale = exp(0.25*lv), deterministic partial sum(lv)
// grid = (16, 24) x 256. 32 FMA per float4 weight load.
// ---------------------------------------------------------------------------
__global__ void __launch_bounds__(256) gemm3_kernel(
    const float* __restrict__ mw, const float* __restrict__ mb,
    const float* __restrict__ lw, const float* __restrict__ lb)
{
    __shared__ float4 s4[8][32];       // 8 rows x 128 floats (one head half)
    __shared__ float red[8][8];

    int tid  = threadIdx.x;
    int row0 = blockIdx.y * 8;
    int head = blockIdx.x >> 3;        // 0 = mu, 1 = lv

    {   // 256 threads load 8 rows x 32 float4
        int r  = tid >> 5;
        int kk = tid & 31;
        s4[r][kk] = ((const float4*)(g_h2 + (row0 + r) * 256 + head * H))[kk];
    }
    __syncthreads();

    int d = (blockIdx.x & 7) * 256 + tid;         // 0..2047 within head
    const float* wrow = (head ? lw : mw) + (size_t)d * H;
    const float* bptr = head ? lb : mb;

    float acc[8];
    #pragma unroll
    for (int r = 0; r < 8; ++r) acc[r] = 0.f;

    #pragma unroll
    for (int kk = 0; kk < 32; ++kk) {
        float4 w = ((const float4*)wrow)[kk];
        #pragma unroll
        for (int r = 0; r < 8; ++r) {
            float4 h = s4[r][kk];
            acc[r] += w.x * h.x + w.y * h.y + w.z * h.z + w.w * h.w;
        }
    }
    float bias = bptr[d];

    if (!head) {
        #pragma unroll
        for (int r = 0; r < 8; ++r)
            g_mu[(size_t)(row0 + r) * D + d] = fmaxf(acc[r] + bias, 0.f);
    } else {
        int lane = tid & 31, wid = tid >> 5;
        #pragma unroll
        for (int r = 0; r < 8; ++r) {
            float v = fmaxf(acc[r] + bias, 0.f);
            g_scale[(size_t)(row0 + r) * D + d] = expf(0.25f * v);
            #pragma unroll
            for (int o = 16; o; o >>= 1) v += __shfl_xor_sync(0xffffffffu, v, o);
            if (lane == 0) red[wid][r] = v;
        }
        __syncthreads();
        if (tid == 0) {
            #pragma unroll
            for (int r = 0; r < 8; ++r) {
                float sum = 0.f;
                #pragma unroll
                for (int k = 0; k < 8; ++k) sum += red[k][r];
                g_lvpart[(row0 + r) * 8 + (blockIdx.x & 7)] = sum;
            }
        }
    }
}

// ---------------------------------------------------------------------------
// Kernel 4 (HBM-bound mainloop): block per (j, group of IG=4 i-rows).
// mu/scale held in REGISTERS (16 regs), no smem -> high occupancy, 4 independent
// row streams per block for MLP. mu/scale L2 traffic = 151 MB (4x reuse).
//   p[i,j,:] = mu[j,:] + eps[i,j,:] * scale[j,:]
//   log_prob[i,j] = -0.5 * sum(eps^2) - 0.25*sum(lv[j]) - 0.5*D*log2pi
// grid = B*(B/IG) = 9216 blocks x 256 threads.
// ---------------------------------------------------------------------------
__global__ void __launch_bounds__(256) main_kernel(
    const float* __restrict__ eps,
    float* __restrict__ p,
    float* __restrict__ lp)
{
    __shared__ float red[8][IG];
    __shared__ float s_t;

    int j   = blockIdx.x % B;
    int ig  = blockIdx.x / B;        // 0..47
    int tid = threadIdx.x;

    const float4* m4 = (const float4*)g_mu    + (size_t)j * (D / 4);
    const float4* s4 = (const float4*)g_scale + (size_t)j * (D / 4);
    float4 m0 = m4[tid], m1 = m4[tid + 256];
    float4 s0 = s4[tid], s1 = s4[tid + 256];

    if (tid == 0) {
        float sum = 0.f;
        #pragma unroll
        for (int k = 0; k < 8; ++k) sum += g_lvpart[j * 8 + k];
        s_t = -0.25f * sum - 0.5f * (float)D * LOG2PI;
    }

    float acc[IG];
    #pragma unroll
    for (int r = 0; r < IG; ++r) {
        size_t row = (size_t)(ig * IG + r) * B + j;
        const float4* e4 = (const float4*)eps + row * (D / 4);
        float4*       p4 = (float4*)p        + row * (D / 4);

        float4 e0 = __ldcs(&e4[tid]);
        float4 e1 = __ldcs(&e4[tid + 256]);
        float4 o0, o1;
        o0.x = fmaf(e0.x, s0.x, m0.x);
        o0.y = fmaf(e0.y, s0.y, m0.y);
        o0.z = fmaf(e0.z, s0.z, m0.z);
        o0.w = fmaf(e0.w, s0.w, m0.w);
        o1.x = fmaf(e1.x, s1.x, m1.x);
        o1.y = fmaf(e1.y, s1.y, m1.y);
        o1.z = fmaf(e1.z, s1.z, m1.z);
        o1.w = fmaf(e1.w, s1.w, m1.w);
        __stcs(&p4[tid], o0);
        __stcs(&p4[tid + 256], o1);
        acc[r] = e0.x * e0.x + e0.y * e0.y + e0.z * e0.z + e0.w * e0.w
               + e1.x * e1.x + e1.y * e1.y + e1.z * e1.z + e1.w * e1.w;
    }

    int lane = tid & 31, wid = tid >> 5;
    #pragma unroll
    for (int r = 0; r < IG; ++r) {
        float v = acc[r];
        #pragma unroll
        for (int o = 16; o; o >>= 1) v += __shfl_xor_sync(0xffffffffu, v, o);
        if (lane == 0) red[wid][r] = v;
    }
    __syncthreads();
    if (tid < IG) {
        float v = 0.f;
        #pragma unroll
        for (int k = 0; k < 8; ++k) v += red[k][tid];
        lp[(size_t)(ig * IG + tid) * B + j] = -0.5f * v + s_t;
    }
}

// ---------------------------------------------------------------------------
extern "C" void kernel_launch(void* const* d_in, const int* in_sizes, int n_in,
                              void* d_out, int out_size)
{
    const float* q     = (const float*)d_in[0];
    const float* eps   = (const float*)d_in[1];
    const float* mu_w1 = (const float*)d_in[2];
    const float* mu_b1 = (const float*)d_in[3];
    const float* mu_w2 = (const float*)d_in[4];
    const float* mu_b2 = (const float*)d_in[5];
    const float* mu_w3 = (const float*)d_in[6];
    const float* mu_b3 = (const float*)d_in[7];
    const float* lv_w1 = (const float*)d_in[8];
    const float* lv_b1 = (const float*)d_in[9];
    const float* lv_w2 = (const float*)d_in[10];
    const float* lv_b2 = (const float*)d_in[11];
    const float* lv_w3 = (const float*)d_in[12];
    const float* lv_b3 = (const float*)d_in[13];

    float* p  = (float*)d_out;                       // [B, B, D]
    float* lp = (float*)d_out + (size_t)B * B * D;   // [B, B]

    gemm1_kernel<<<dim3(8, 48), 256>>>(q, mu_w1, mu_b1, lv_w1, lv_b1);
    gemm2_kernel<<<B / 8, 256>>>(mu_w2, mu_b2, lv_w2, lv_b2);
    gemm3_kernel<<<dim3(16, 24), 256>>>(mu_w3, mu_b3, lv_w3, lv_b3);
    main_kernel<<<B * (B / IG), 256>>>(eps, p, lp);
}